// round 2
// baseline (speedup 1.0000x reference)
#include <cuda_runtime.h>

#define BB 4
#define CC 64
#define NN 4096
#define TILE 128
#define KB 16
#define NTILES (NN / TILE)                    // 32
#define NPAIRS (NTILES * (NTILES + 1) / 2)    // 528

// Scratch (no allocations allowed): per-point squared norms + global accumulator.
__device__ float  d_r[BB * NN];
__device__ double d_acc;

__global__ void init_kernel() { d_acc = 0.0; }

// r[b,n] = sum_c F[b,c,n]^2   (sequential over c, fp32 FMA — must match the
// accumulation order of the main kernel's k-loop so D(n,n) == 0 exactly)
__global__ void r_kernel(const float* __restrict__ F) {
    int p = blockIdx.x * blockDim.x + threadIdx.x;   // 0 .. B*N-1
    int b = p >> 12;
    int n = p & (NN - 1);
    const float* f = F + (size_t)b * CC * NN + n;
    float s = 0.f;
#pragma unroll
    for (int c = 0; c < CC; ++c) {
        float v = f[(size_t)c * NN];
        s = fmaf(v, v, s);
    }
    d_r[p] = s;
}

// One block computes a 128x128 tile of the pairwise matrix for batch b,
// tile-pair (i,j) with j >= i (symmetry: off-diagonal tiles weighted 2x),
// fused with the SGPN loss epilogue and a block reduction.
__launch_bounds__(256, 2)
__global__ void tile_kernel(const float* __restrict__ F, const int* __restrict__ tgt) {
    // Decode triangular tile pair from blockIdx.x
    int rem = blockIdx.x;
    int i = 0;
#pragma unroll 1
    while (rem >= NTILES - i) { rem -= NTILES - i; ++i; }
    const int j = i + rem;
    const int b = blockIdx.y;

    const int n0 = i * TILE;   // "row" side (n index)  -> A
    const int m0 = j * TILE;   // "col" side (m index)  -> B

    __shared__ float As[KB][TILE + 4];
    __shared__ float Bs[KB][TILE + 4];
    __shared__ float r_row[TILE], r_col[TILE];
    __shared__ int   g_row[TILE], g_col[TILE];
    __shared__ float red[256];

    const int tid = threadIdx.x;

    if (tid < TILE) {
        r_row[tid] = d_r[b * NN + n0 + tid];
        r_col[tid] = d_r[b * NN + m0 + tid];
        g_row[tid] = tgt[b * NN + n0 + tid];
        g_col[tid] = tgt[b * NN + m0 + tid];
    }

    const float* Fb = F + (size_t)b * CC * NN;

    float acc[8][8];
#pragma unroll
    for (int y = 0; y < 8; ++y)
#pragma unroll
        for (int x = 0; x < 8; ++x) acc[y][x] = 0.f;

    // Warp layout: 8 warps as 4 (row-dir) x 2 (col-dir); lane as 4x8.
    const int lane = tid & 31, warp = tid >> 5;
    const int wm = warp >> 1, wn = warp & 1;
    const int row = wm * 32 + (lane >> 3) * 8;   // n-offset within tile
    const int col = wn * 64 + (lane & 7) * 8;    // m-offset within tile

    // Load indices for the smem staging: 512 float4 per tile side, 2 per thread.
    const int k_a = tid >> 5;          // 0..7
    const int x4a = (tid & 31) * 4;    // 0..124

#pragma unroll 1
    for (int k0 = 0; k0 < CC; k0 += KB) {
        // Stage As (rows n0..n0+127) and Bs (rows m0..m0+127) for KB k-slices.
#pragma unroll
        for (int it = 0; it < 2; ++it) {
            int k = k_a + it * 8;
            const float4 va = *(const float4*)(Fb + (size_t)(k0 + k) * NN + n0 + x4a);
            const float4 vb = *(const float4*)(Fb + (size_t)(k0 + k) * NN + m0 + x4a);
            *(float4*)&As[k][x4a] = va;
            *(float4*)&Bs[k][x4a] = vb;
        }
        __syncthreads();

#pragma unroll
        for (int k = 0; k < KB; ++k) {
            float a[8], bf[8];
            *(float4*)&a[0]  = *(const float4*)&As[k][row];
            *(float4*)&a[4]  = *(const float4*)&As[k][row + 4];
            *(float4*)&bf[0] = *(const float4*)&Bs[k][col];
            *(float4*)&bf[4] = *(const float4*)&Bs[k][col + 4];
#pragma unroll
            for (int y = 0; y < 8; ++y)
#pragma unroll
                for (int x = 0; x < 8; ++x)
                    acc[y][x] = fmaf(a[y], bf[x], acc[y][x]);
        }
        __syncthreads();
    }

    // Fused epilogue: D, same/diff, margin term, label weight; local fp32 sum.
    float lsum = 0.f;
#pragma unroll
    for (int y = 0; y < 8; ++y) {
        const float rn  = r_row[row + y];
        const int   gy  = g_row[row + y];
        const float tfn = (float)gy;
        const int   gn  = n0 + row + y;
#pragma unroll
        for (int x = 0; x < 8; ++x) {
            const float rm = r_col[col + x];
            const int   gx = g_col[col + x];
            float D = fmaf(-2.f, acc[y][x], rn + rm);
            D = fmaxf(D, 0.f);
            const bool same = (gn == m0 + col + x) || (gy == gx && gy != -1);
            const float term = same ? D : 2.0f * fmaxf(0.8f - D, 0.f);
            lsum = fmaf(term * tfn, (float)gx, lsum);
        }
    }

    // Block reduce -> double atomic (off-diagonal tiles count twice).
    red[tid] = lsum;
    __syncthreads();
#pragma unroll
    for (int s = 128; s > 0; s >>= 1) {
        if (tid < s) red[tid] += red[tid + s];
        __syncthreads();
    }
    if (tid == 0) {
        const double mult = (i == j) ? 1.0 : 2.0;
        atomicAdd(&d_acc, (double)red[0] * mult);
    }
}

__global__ void fin_kernel(float* out) {
    out[0] = (float)(d_acc / ((double)BB * NN * NN));
}

extern "C" void kernel_launch(void* const* d_in, const int* in_sizes, int n_in,
                              void* d_out, int out_size) {
    // Select inputs by element count (robust to ordering):
    //   Fsim: B*C*N = 1048576 fp32, target: B*N = 16384 int32, l0_points unused.
    const float* F  = nullptr;
    const int*   tg = nullptr;
    for (int k = 0; k < n_in; ++k) {
        if (in_sizes[k] == BB * CC * NN)      F  = (const float*)d_in[k];
        else if (in_sizes[k] == BB * NN)      tg = (const int*)d_in[k];
    }
    float* out = (float*)d_out;

    init_kernel<<<1, 1>>>();
    r_kernel<<<(BB * NN) / 256, 256>>>(F);
    tile_kernel<<<dim3(NPAIRS, BB), 256>>>(F, tg);
    fin_kernel<<<1, 1>>>(out);
}

// round 4
// speedup vs baseline: 1.0012x; 1.0012x over previous
#include <cuda_runtime.h>

#define BB 4
#define CC 64
#define NN 4096
#define TILE 128
#define KB 16
#define NTILES (NN / TILE)                    // 32
#define NPAIRS (NTILES * (NTILES + 1) / 2)    // 528

// Scratch (no allocations allowed): per-point squared norms + global accumulator.
__device__ float  d_r[BB * NN];
__device__ double d_acc;

__global__ void init_kernel() { d_acc = 0.0; }

// r[b,n] = sum_c F[b,c,n]^2  (sequential fp32 fma chain — must match the
// per-element accumulation order of the main kernel so D(n,n) == 0 exactly)
__global__ void r_kernel(const float* __restrict__ F) {
    int p = blockIdx.x * blockDim.x + threadIdx.x;   // 0 .. B*N-1
    int b = p >> 12;
    int n = p & (NN - 1);
    const float* f = F + (size_t)b * CC * NN + n;
    float s = 0.f;
#pragma unroll
    for (int c = 0; c < CC; ++c) {
        float v = f[(size_t)c * NN];
        s = fmaf(v, v, s);
    }
    d_r[p] = s;
}

// ---- packed fp32x2 helpers (SASS FFMA2; only reachable via PTX) ----
__device__ __forceinline__ unsigned long long pack2(float lo, float hi) {
    unsigned long long r;
    asm("mov.b64 %0, {%1, %2};" : "=l"(r) : "f"(lo), "f"(hi));
    return r;
}
__device__ __forceinline__ void fma2(unsigned long long& d,
                                     unsigned long long a,
                                     unsigned long long b) {
    asm("fma.rn.f32x2 %0, %1, %2, %0;" : "+l"(d) : "l"(a), "l"(b));
}
__device__ __forceinline__ float2 unpack2(unsigned long long v) {
    float2 r;
    asm("mov.b64 {%0, %1}, %2;" : "=f"(r.x), "=f"(r.y) : "l"(v));
    return r;
}

// One block computes a 128x128 tile of the pairwise matrix for batch b,
// tile-pair (i,j) with j >= i (symmetry: off-diagonal tiles weighted 2x),
// fused with the SGPN loss epilogue and a block reduction.
__launch_bounds__(256, 2)
__global__ void tile_kernel(const float* __restrict__ F, const int* __restrict__ tgt) {
    // Decode triangular tile pair from blockIdx.x
    int rem = blockIdx.x;
    int i = 0;
#pragma unroll 1
    while (rem >= NTILES - i) { rem -= NTILES - i; ++i; }
    const int j = i + rem;
    const int b = blockIdx.y;

    const int n0 = i * TILE;   // "row" side (n index)  -> A
    const int m0 = j * TILE;   // "col" side (m index)  -> B

    __shared__ float As[KB][TILE + 4];
    __shared__ float Bs[KB][TILE + 4];
    __shared__ float r_row[TILE], r_col[TILE];
    __shared__ int   g_row[TILE], g_col[TILE];
    __shared__ float red[256];

    const int tid = threadIdx.x;

    if (tid < TILE) {
        r_row[tid] = d_r[b * NN + n0 + tid];
        r_col[tid] = d_r[b * NN + m0 + tid];
        g_row[tid] = tgt[b * NN + n0 + tid];
        g_col[tid] = tgt[b * NN + m0 + tid];
    }

    const float* Fb = F + (size_t)b * CC * NN;

    // acc[y][p] holds the packed pair (col+2p, col+2p+1) for row 'row+y'.
    unsigned long long acc[8][4];
#pragma unroll
    for (int y = 0; y < 8; ++y)
#pragma unroll
        for (int p = 0; p < 4; ++p) acc[y][p] = 0ull;

    // Warp layout: 8 warps as 4 (row-dir) x 2 (col-dir); lane as 4x8.
    const int lane = tid & 31, warp = tid >> 5;
    const int wm = warp >> 1, wn = warp & 1;
    const int row = wm * 32 + (lane >> 3) * 8;   // n-offset within tile
    const int col = wn * 64 + (lane & 7) * 8;    // m-offset within tile

    // smem staging indices: 512 float4 per side, 2 per thread.
    const int k_a = tid >> 5;          // 0..7
    const int x4a = (tid & 31) * 4;    // 0..124

#pragma unroll 1
    for (int k0 = 0; k0 < CC; k0 += KB) {
#pragma unroll
        for (int it = 0; it < 2; ++it) {
            int k = k_a + it * 8;
            const float4 va = *(const float4*)(Fb + (size_t)(k0 + k) * NN + n0 + x4a);
            const float4 vb = *(const float4*)(Fb + (size_t)(k0 + k) * NN + m0 + x4a);
            *(float4*)&As[k][x4a] = va;
            *(float4*)&Bs[k][x4a] = vb;
        }
        __syncthreads();

#pragma unroll
        for (int k = 0; k < KB; ++k) {
            float a[8];
            *(float4*)&a[0] = *(const float4*)&As[k][row];
            *(float4*)&a[4] = *(const float4*)&As[k][row + 4];
            // B pairs: consecutive floats, naturally packed; row stride
            // (TILE+4)*4 = 528 B is 16B-aligned, col*4 is 32B-aligned.
            const ulonglong2 b01 = *(const ulonglong2*)&Bs[k][col];
            const ulonglong2 b23 = *(const ulonglong2*)&Bs[k][col + 4];
            unsigned long long bp[4] = { b01.x, b01.y, b23.x, b23.y };
#pragma unroll
            for (int y = 0; y < 8; ++y) {
                const unsigned long long ap = pack2(a[y], a[y]);
#pragma unroll
                for (int p = 0; p < 4; ++p) fma2(acc[y][p], ap, bp[p]);
            }
        }
        __syncthreads();
    }

    // Fused epilogue: D, same/diff, margin term, label weight; local fp32 sum.
    float lsum = 0.f;
#pragma unroll
    for (int y = 0; y < 8; ++y) {
        const float rn  = r_row[row + y];
        const int   gy  = g_row[row + y];
        const float tfn = (float)gy;
        const int   gn  = n0 + row + y;
#pragma unroll
        for (int p = 0; p < 4; ++p) {
            const float2 g2 = unpack2(acc[y][p]);
#pragma unroll
            for (int h = 0; h < 2; ++h) {
                const int   x  = 2 * p + h;
                const float gv = h ? g2.y : g2.x;
                const float rm = r_col[col + x];
                const int   gx = g_col[col + x];
                float D = fmaf(-2.f, gv, rn + rm);
                D = fmaxf(D, 0.f);
                const bool same = (gn == m0 + col + x) || (gy == gx && gy != -1);
                const float term = same ? D : 2.0f * fmaxf(0.8f - D, 0.f);
                lsum = fmaf(term * tfn, (float)gx, lsum);
            }
        }
    }

    // Block reduce -> double atomic (off-diagonal tiles count twice).
    red[tid] = lsum;
    __syncthreads();
#pragma unroll
    for (int s = 128; s > 0; s >>= 1) {
        if (tid < s) red[tid] += red[tid + s];
        __syncthreads();
    }
    if (tid == 0) {
        const double mult = (i == j) ? 1.0 : 2.0;
        atomicAdd(&d_acc, (double)red[0] * mult);
    }
}

__global__ void fin_kernel(float* out) {
    out[0] = (float)(d_acc / ((double)BB * NN * NN));
}

extern "C" void kernel_launch(void* const* d_in, const int* in_sizes, int n_in,
                              void* d_out, int out_size) {
    // Select inputs by element count (robust to ordering):
    //   Fsim: B*C*N = 1048576 fp32, target: B*N = 16384 int32, l0_points unused.
    const float* F  = nullptr;
    const int*   tg = nullptr;
    for (int k = 0; k < n_in; ++k) {
        if (in_sizes[k] == BB * CC * NN)      F  = (const float*)d_in[k];
        else if (in_sizes[k] == BB * NN)      tg = (const int*)d_in[k];
    }
    float* out = (float*)d_out;

    init_kernel<<<1, 1>>>();
    r_kernel<<<(BB * NN) / 256, 256>>>(F);
    tile_kernel<<<dim3(NPAIRS, BB), 256>>>(F, tg);
    fin_kernel<<<1, 1>>>(out);
}

// round 7
// speedup vs baseline: 2.7165x; 2.7132x over previous
#include <cuda_runtime.h>
#include <cuda_bf16.h>
#include <cstdint>

#define BB 4
#define CC 64
#define NN 4096
#define TILE 128
#define NTILES 32                     // NN/TILE
#define NPAIRS 528                    // NTILES*(NTILES+1)/2
#define GRID_X NPAIRS
#define STRB 144                      // smem row stride in bytes (64 bf16 = 128B + 16B pad)

// Scratch (static device arrays; no allocations allowed)
__device__ __nv_bfloat16 d_Ft[(size_t)BB * NN * CC];   // [b][n][c], rows = 128B contiguous
__device__ float  d_r[BB * NN];
__device__ double d_acc;
__device__ int    d_count;

// ---------------- helpers ----------------
__device__ __forceinline__ uint32_t smem_u32(const void* p) {
    uint32_t a;
    asm("{ .reg .u64 t; cvta.to.shared.u64 t, %1; cvt.u32.u64 %0, t; }" : "=r"(a) : "l"(p));
    return a;
}
__device__ __forceinline__ void ldsm4(uint32_t* r, uint32_t addr) {
    asm volatile("ldmatrix.sync.aligned.m8n8.x4.shared.b16 {%0,%1,%2,%3}, [%4];"
                 : "=r"(r[0]), "=r"(r[1]), "=r"(r[2]), "=r"(r[3]) : "r"(addr));
}
__device__ __forceinline__ void mma_bf16(float* c, const uint32_t* a, const uint32_t* b) {
    asm volatile("mma.sync.aligned.m16n8k16.row.col.f32.bf16.bf16.f32 "
                 "{%0,%1,%2,%3}, {%4,%5,%6,%7}, {%8,%9}, {%0,%1,%2,%3};"
                 : "+f"(c[0]), "+f"(c[1]), "+f"(c[2]), "+f"(c[3])
                 : "r"(a[0]), "r"(a[1]), "r"(a[2]), "r"(a[3]), "r"(b[0]), "r"(b[1]));
}

// ---------------- prep: init + transpose F->Ft (bf16) + r from rounded values ----
// grid (NN/64, BB), block 256
__global__ void prep_kernel(const float* __restrict__ F) {
    if (blockIdx.x == 0 && blockIdx.y == 0 && threadIdx.x == 0) { d_acc = 0.0; d_count = 0; }

    const int b  = blockIdx.y;
    const int n0 = blockIdx.x * 64;
    __shared__ float t[CC][65];

    const int tid = threadIdx.x;
    const int c4 = tid >> 6;          // 0..3
    const int nl = tid & 63;          // 0..63
    for (int cc0 = 0; cc0 < CC; cc0 += 4) {
        const int c = cc0 + c4;
        t[c][nl] = F[((size_t)b * CC + c) * NN + n0 + nl];
    }
    __syncthreads();

    // thread = (n_loc 0..63, q 0..3): write 16 bf16 (8 u32) of one row + partial r
    const int n_loc = tid >> 2;
    const int q     = tid & 3;
    uint32_t* out = reinterpret_cast<uint32_t*>(d_Ft) + ((size_t)(b * NN + n0 + n_loc)) * (CC / 2);
    float s = 0.f;
#pragma unroll
    for (int k = 0; k < 16; k += 2) {
        const int c = q * 16 + k;
        const __nv_bfloat16 b0 = __float2bfloat16_rn(t[c][n_loc]);
        const __nv_bfloat16 b1 = __float2bfloat16_rn(t[c + 1][n_loc]);
        const float f0 = __bfloat162float(b0), f1 = __bfloat162float(b1);
        s = fmaf(f0, f0, s);
        s = fmaf(f1, f1, s);
        out[(c >> 1)] = (uint32_t)__bfloat16_as_ushort(b0) |
                        ((uint32_t)__bfloat16_as_ushort(b1) << 16);
    }
    s += __shfl_xor_sync(0xffffffffu, s, 1);
    s += __shfl_xor_sync(0xffffffffu, s, 2);
    if (q == 0) d_r[b * NN + n0 + n_loc] = s;
}

// ---------------- tensor-core tile kernel (one 128x128 tile per block) ----------------
// grid (NPAIRS, BB), block 256 (8 warps as 4x2; warp = 32x64 of the tile)
__global__ __launch_bounds__(256)
void tile_kernel(const int* __restrict__ tgt, float* __restrict__ out) {
    __shared__ __align__(16) char sA[TILE * STRB];   // 18432 B
    __shared__ __align__(16) char sB[TILE * STRB];   // 18432 B
    __shared__ float  r_row[TILE], gf_row[TILE];
    __shared__ float2 rg_col[TILE];
    __shared__ float  red[8];

    const int tid  = threadIdx.x;
    const int wid  = tid >> 5;
    const int lane = tid & 31;

    // decode triangular pair (i <= j)
    int rem = blockIdx.x;
    int i = 0;
#pragma unroll 1
    while (rem >= NTILES - i) { rem -= NTILES - i; ++i; }
    const int j  = i + rem;
    const int b  = blockIdx.y;
    const int n0 = i * TILE;
    const int m0 = j * TILE;
    const bool diagtile = (i == j);

    // ---- stage tiles: 128 rows x 128B each, padded to 144B rows in smem ----
    const uint4* srcA = (const uint4*)(d_Ft + ((size_t)(b * NN + n0)) * CC);
    const uint4* srcB = diagtile ? srcA : (const uint4*)(d_Ft + ((size_t)(b * NN + m0)) * CC);
#pragma unroll
    for (int it = 0; it < 4; ++it) {
        const int u   = tid + it * 256;      // 0..1023
        const int row = u >> 3, seg = u & 7;
        *(uint4*)(sA + row * STRB + seg * 16) = srcA[u];
        *(uint4*)(sB + row * STRB + seg * 16) = srcB[u];
    }
    if (tid < TILE) {
        r_row[tid]  = d_r[b * NN + n0 + tid];
        gf_row[tid] = (float)tgt[b * NN + n0 + tid];
        rg_col[tid] = make_float2(d_r[b * NN + m0 + tid], (float)tgt[b * NN + m0 + tid]);
    }
    __syncthreads();

    // ---- warp-level GEMM: warp (wm, wn) computes rows wm*32..+31, cols wn*64..+63 ----
    const int wm = wid >> 1, wn = wid & 1;
    const int r8 = lane & 7, id = lane >> 3;

    const uint32_t smA = smem_u32(sA), smB = smem_u32(sB);
    // A (row-major m x k): mat0:(m,k) mat1:(m+8,k) mat2:(m,k+8) mat3:(m+8,k+8)
    const uint32_t aBase = smA + (uint32_t)((wm * 32 + ((id & 1) << 3) + r8) * STRB + ((id >> 1) << 4));
    // B ([n][k] row-major): mat0:(n,k) mat1:(n,k+8) mat2:(n+8,k) mat3:(n+8,k+8)
    const uint32_t bBase = smB + (uint32_t)((wn * 64 + ((id >> 1) << 3) + r8) * STRB + ((id & 1) << 4));

    float acc[2][8][4];
#pragma unroll
    for (int mi = 0; mi < 2; ++mi)
#pragma unroll
        for (int ni = 0; ni < 8; ++ni)
#pragma unroll
            for (int e = 0; e < 4; ++e) acc[mi][ni][e] = 0.f;

#pragma unroll
    for (int ks = 0; ks < 4; ++ks) {
        uint32_t a[2][4], bf[4][4];
        ldsm4(a[0], aBase + ks * 32);
        ldsm4(a[1], aBase + 16 * STRB + ks * 32);
#pragma unroll
        for (int nb = 0; nb < 4; ++nb)
            ldsm4(bf[nb], bBase + nb * 16 * STRB + ks * 32);
#pragma unroll
        for (int mi = 0; mi < 2; ++mi)
#pragma unroll
            for (int ni = 0; ni < 8; ++ni)
                mma_bf16(acc[mi][ni], a[mi], &bf[ni >> 1][(ni & 1) * 2]);
    }

    // ---- fused epilogue ----
    const int quad = lane >> 2, tq = lane & 3;
    float rn[2][2], gy[2][2];
    int   rw[2][2];
#pragma unroll
    for (int mi = 0; mi < 2; ++mi)
#pragma unroll
        for (int h = 0; h < 2; ++h) {
            const int row = wm * 32 + mi * 16 + h * 8 + quad;
            rw[mi][h] = row;
            rn[mi][h] = r_row[row];
            gy[mi][h] = gf_row[row];
        }

    float lsum = 0.f;
#pragma unroll
    for (int ni = 0; ni < 8; ++ni) {
#pragma unroll
        for (int e = 0; e < 2; ++e) {
            const int col = wn * 64 + ni * 8 + tq * 2 + e;
            const float2 rg = rg_col[col];
#pragma unroll
            for (int mi = 0; mi < 2; ++mi)
#pragma unroll
                for (int h = 0; h < 2; ++h) {
                    const float g = acc[mi][ni][h * 2 + e];
                    float D = fmaf(-2.f, g, rn[mi][h] + rg.x);
                    D = fmaxf(D, 0.f);
                    const float neg = fmaxf(fmaf(-2.f, D, 1.6f), 0.f);  // 2*max(0.8-D,0)
                    const float gv = gy[mi][h];
                    const bool same = (gv == rg.y) && (gv != -1.0f);
                    float sel = same ? D : neg;
                    if (diagtile && rw[mi][h] == col) sel = 0.f;        // exact diagonal zero
                    lsum = fmaf(sel * gv, rg.y, lsum);                  // * t_n * t_m
                }
        }
    }
    if (!diagtile) lsum *= 2.f;   // symmetry

    // ---- block reduce -> one double atomic; last block finalizes output ----
#pragma unroll
    for (int o = 16; o; o >>= 1) lsum += __shfl_xor_sync(0xffffffffu, lsum, o);
    if (lane == 0) red[wid] = lsum;
    __syncthreads();
    if (tid == 0) {
        float s = 0.f;
#pragma unroll
        for (int w = 0; w < 8; ++w) s += red[w];
        atomicAdd(&d_acc, (double)s);
        __threadfence();
        const int done = atomicAdd(&d_count, 1);
        if (done == GRID_X * BB - 1) {
            d_count = 0;
            const double total = atomicAdd(&d_acc, 0.0);
            out[0] = (float)(total / ((double)BB * NN * NN));
        }
    }
}

extern "C" void kernel_launch(void* const* d_in, const int* in_sizes, int n_in,
                              void* d_out, int out_size) {
    // Select inputs by element count: Fsim = B*C*N, target = B*N (l0_points unused)
    const float* F  = nullptr;
    const int*   tg = nullptr;
    for (int k = 0; k < n_in; ++k) {
        if (in_sizes[k] == BB * CC * NN) F  = (const float*)d_in[k];
        else if (in_sizes[k] == BB * NN) tg = (const int*)d_in[k];
    }
    float* out = (float*)d_out;

    prep_kernel<<<dim3(NN / 64, BB), 256>>>(F);
    tile_kernel<<<dim3(GRID_X, BB), 256>>>(tg, out);
}